// round 1
// baseline (speedup 1.0000x reference)
#include <cuda_runtime.h>
#include <math.h>

// ---------------- problem constants ----------------
#define BB   16
#define CC   256
#define HH   64
#define WW   64
#define MM   4096          // H*W
#define HID  256
#define NN   300
#define SDIM 64
#define NHH  4
#define HDD  16
#define NCC  80

// output layout (flattened tuple: boxes, scores, cls, maps, div, sf)
#define OFF_BOXES  0LL
#define OFF_SCORES 19200LL
#define OFF_CLS    24000LL
#define OFF_MAPS   408000LL
#define OFF_DIV    20068800LL
#define OFF_SF     20068801LL

// ---------------- device scratch (static: no allocs allowed) ----------------
__device__ float g_feats[BB * 128 * MM];        // 32 MB
__device__ float g_keys [BB * 64 * MM];         // 16 MB
__device__ float g_vals [BB * 256 * MM];        // 64 MB
__device__ float g_pos  [128 * MM];             // 2 MB
__device__ float g_posk [64 * MM];              // 1 MB
__device__ float g_posv [256 * MM];             // 4 MB
__device__ float g_logits[(long long)BB * 4 * NN * MM]; // 314 MB
__device__ float g_invn [BB * NN];
__device__ float g_sfp  [BB * 8 * NN * HID];    // split-K partials, 39 MB
__device__ float g_sf   [BB * NN * HID];        // 4.9 MB (16B-aligned copy of sf)
__device__ float g_h1   [BB * NN * 256];
__device__ float g_h2   [BB * NN * 128];
__device__ float g_bns  [128];
__device__ float g_bnt  [128];
__device__ float g_divpart[256];

// ---------------- small kernels ----------------
__global__ void init_kernel(const float* __restrict__ fp_b, const float* __restrict__ bn_g,
                            const float* __restrict__ bn_b, const float* __restrict__ bn_m,
                            const float* __restrict__ bn_v) {
    int t = threadIdx.x;
    if (t < 128) {
        float s = bn_g[t] * rsqrtf(bn_v[t] + 1e-5f);
        g_bns[t] = s;
        g_bnt[t] = (fp_b[t] - bn_m[t]) * s + bn_b[t];
    }
}

__global__ void pos_kernel(const float* __restrict__ pos_w, const float* __restrict__ pos_b) {
    int m = blockIdx.x * 256 + threadIdx.x;   // 0..4095
    int o = blockIdx.y;                       // 0..127
    int hh = m >> 6, ww = m & 63;
    float y = -1.0f + 2.0f * (float)hh / 63.0f;
    float x = -1.0f + 2.0f * (float)ww / 63.0f;
    g_pos[(long long)o * MM + m] = pos_w[o * 2] * y + pos_w[o * 2 + 1] * x + pos_b[o];
}

// ---------------- GEMM NN: C[o,m] = sum_k W[o, k] * X[k, m]  (X row-major over m) ----------------
// EPI 0: alpha*acc + bias[o]   EPI 1: relu(acc*v1[o]+v2[o])   EPI 2: acc + C0[o*M+m]
// ZMAP 0: linear z strides     ZMAP 1: logits mapping (z = b*4+h)
#define TILE 128
#define BK   16

template<int EPI, int ZMAP>
__global__ void __launch_bounds__(256) gemm_nn(
    const float* __restrict__ Wb, int ldw,
    const float* __restrict__ Xb, float* __restrict__ Cb,
    int O, int M, int K,
    long long wz, long long xz, long long cz,
    const float* __restrict__ v1, const float* __restrict__ v2,
    float alpha, const float* __restrict__ C0)
{
    __shared__ float Ws[BK][TILE + 4];
    __shared__ float Xs[BK][TILE + 4];
    int z = blockIdx.z;
    const float* W; const float* X; float* C;
    if (ZMAP == 0) { W = Wb + wz * z; X = Xb + xz * z; C = Cb + cz * z; }
    else {
        int b = z >> 2, h = z & 3;
        W = Wb + h * 16;
        X = Xb + ((long long)(b * 64 + h * 16)) * M;
        C = Cb + (long long)z * O * M;
    }
    int t = threadIdx.x, tx = t & 15, ty = t >> 4;
    int oB = blockIdx.y * TILE, mB = blockIdx.x * TILE;

    float acc[8][8];
#pragma unroll
    for (int i = 0; i < 8; i++)
#pragma unroll
        for (int j = 0; j < 8; j++) acc[i][j] = 0.f;

    for (int k0 = 0; k0 < K; k0 += BK) {
#pragma unroll
        for (int r = 0; r < 2; r++) {
            int idx = t + r * 256;
            int row = idx >> 2, kq = (idx & 3) * 4;
            float4 v = make_float4(0.f, 0.f, 0.f, 0.f);
            int o = oB + row;
            if (o < O) v = *(const float4*)(W + (long long)o * ldw + k0 + kq);
            Ws[kq + 0][row] = v.x; Ws[kq + 1][row] = v.y;
            Ws[kq + 2][row] = v.z; Ws[kq + 3][row] = v.w;
        }
#pragma unroll
        for (int r = 0; r < 2; r++) {
            int idx = t + r * 256;
            int row = idx >> 5, cq = (idx & 31) * 4;
            float4 v = *(const float4*)(X + (long long)(k0 + row) * M + mB + cq);
            *(float4*)&Xs[row][cq] = v;
        }
        __syncthreads();
#pragma unroll
        for (int k = 0; k < BK; k++) {
            float a[8], bv[8];
            *(float4*)&a[0]  = *(const float4*)&Ws[k][ty * 4];
            *(float4*)&a[4]  = *(const float4*)&Ws[k][ty * 4 + 64];
            *(float4*)&bv[0] = *(const float4*)&Xs[k][tx * 4];
            *(float4*)&bv[4] = *(const float4*)&Xs[k][tx * 4 + 64];
#pragma unroll
            for (int i = 0; i < 8; i++)
#pragma unroll
                for (int j = 0; j < 8; j++) acc[i][j] += a[i] * bv[j];
        }
        __syncthreads();
    }
#pragma unroll
    for (int i = 0; i < 8; i++) {
        int o = oB + (i < 4 ? ty * 4 + i : 64 + ty * 4 + i - 4);
        if (o >= O) continue;
        float e1 = 0.f, e2 = 0.f, bo = 0.f;
        if (EPI == 1) { e1 = v1[o]; e2 = v2[o]; }
        if (EPI == 0 && v1) bo = v1[o];
#pragma unroll
        for (int j = 0; j < 8; j++) {
            int m = mB + (j < 4 ? tx * 4 + j : 64 + tx * 4 + j - 4);
            if (m >= M) continue;
            float v = acc[i][j];
            if (EPI == 0)      v = alpha * v + bo;
            else if (EPI == 1) v = fmaxf(v * e1 + e2, 0.f);
            else               v = v + C0[(long long)o * M + m];
            C[(long long)o * M + m] = v;
        }
    }
}

// ---------------- GEMM NT: C[i,j] = sum_k A[i,k]*B[j,k]  (+bias[j]) ----------------
// EPI 0: +bias  EPI 1: relu(+bias)  EPI 2: sigmoid(+bias)
template<int EPI, bool SPLIT>
__global__ void __launch_bounds__(256) gemm_nt(
    const float* __restrict__ Ab, const float* __restrict__ Bb, float* __restrict__ Cb,
    int I, int J, int K,
    long long az, long long bz, long long cz,
    const float* __restrict__ bias,
    int nsplit, long long scz)
{
    __shared__ float As[BK][TILE + 4];
    __shared__ float Bs[BK][TILE + 4];
    int zz = blockIdx.z;
    int z = SPLIT ? zz / nsplit : zz;
    int s = SPLIT ? zz % nsplit : 0;
    const float* A = Ab + az * z;
    const float* B = Bb + bz * z;
    float* C = Cb + cz * z + (SPLIT ? scz * s : 0);
    int Kc = SPLIT ? K / nsplit : K;
    int kStart = s * Kc;

    int t = threadIdx.x, tx = t & 15, ty = t >> 4;
    int iB = blockIdx.y * TILE, jB = blockIdx.x * TILE;

    float acc[8][8];
#pragma unroll
    for (int i = 0; i < 8; i++)
#pragma unroll
        for (int j = 0; j < 8; j++) acc[i][j] = 0.f;

    for (int k0 = kStart; k0 < kStart + Kc; k0 += BK) {
#pragma unroll
        for (int r = 0; r < 2; r++) {
            int idx = t + r * 256;
            int row = idx >> 2, kq = (idx & 3) * 4;
            float4 v = make_float4(0.f, 0.f, 0.f, 0.f);
            int i = iB + row;
            if (i < I) v = *(const float4*)(A + (long long)i * K + k0 + kq);
            As[kq + 0][row] = v.x; As[kq + 1][row] = v.y;
            As[kq + 2][row] = v.z; As[kq + 3][row] = v.w;
        }
#pragma unroll
        for (int r = 0; r < 2; r++) {
            int idx = t + r * 256;
            int row = idx >> 2, kq = (idx & 3) * 4;
            float4 v = make_float4(0.f, 0.f, 0.f, 0.f);
            int j = jB + row;
            if (j < J) v = *(const float4*)(B + (long long)j * K + k0 + kq);
            Bs[kq + 0][row] = v.x; Bs[kq + 1][row] = v.y;
            Bs[kq + 2][row] = v.z; Bs[kq + 3][row] = v.w;
        }
        __syncthreads();
#pragma unroll
        for (int k = 0; k < BK; k++) {
            float a[8], bv[8];
            *(float4*)&a[0]  = *(const float4*)&As[k][ty * 4];
            *(float4*)&a[4]  = *(const float4*)&As[k][ty * 4 + 64];
            *(float4*)&bv[0] = *(const float4*)&Bs[k][tx * 4];
            *(float4*)&bv[4] = *(const float4*)&Bs[k][tx * 4 + 64];
#pragma unroll
            for (int i = 0; i < 8; i++)
#pragma unroll
                for (int j = 0; j < 8; j++) acc[i][j] += a[i] * bv[j];
        }
        __syncthreads();
    }
#pragma unroll
    for (int i = 0; i < 8; i++) {
        int ii = iB + (i < 4 ? ty * 4 + i : 64 + ty * 4 + i - 4);
        if (ii >= I) continue;
#pragma unroll
        for (int j = 0; j < 8; j++) {
            int jj = jB + (j < 4 ? tx * 4 + j : 64 + tx * 4 + j - 4);
            if (jj >= J) continue;
            float v = acc[i][j];
            if (bias) v += bias[jj];
            if (EPI == 1) v = fmaxf(v, 0.f);
            else if (EPI == 2) v = 1.0f / (1.0f + __expf(-v));
            C[(long long)ii * J + jj] = v;
        }
    }
}

// ---------------- softmax over m (4096), per (b,n); head-mean; row inv-norm ----------------
__global__ void softmax_kernel(const float* __restrict__ logits,
                               float* __restrict__ attn, float* __restrict__ invn)
{
    extern __shared__ float sm[];     // 4 * 4096 floats
    __shared__ float red[256];
    int bn = blockIdx.x;
    int b = bn / NN, n = bn - b * NN;
    int t = threadIdx.x;
#pragma unroll
    for (int h = 0; h < 4; h++) {
        const float* src = logits + ((long long)(b * 4 + h) * NN + n) * MM;
        for (int m = t; m < MM; m += 256) sm[h * MM + m] = src[m];
    }
    __syncthreads();
    float mx[4], rs[4];
#pragma unroll
    for (int h = 0; h < 4; h++) {
        float lm = -1e30f;
        for (int m = t; m < MM; m += 256) lm = fmaxf(lm, sm[h * MM + m]);
        red[t] = lm; __syncthreads();
        for (int k = 128; k > 0; k >>= 1) { if (t < k) red[t] = fmaxf(red[t], red[t + k]); __syncthreads(); }
        mx[h] = red[0]; __syncthreads();
        float ls = 0.f;
        for (int m = t; m < MM; m += 256) ls += __expf(sm[h * MM + m] - mx[h]);
        red[t] = ls; __syncthreads();
        for (int k = 128; k > 0; k >>= 1) { if (t < k) red[t] += red[t + k]; __syncthreads(); }
        rs[h] = 0.25f / red[0]; __syncthreads();
    }
    float ss = 0.f;
    float* dst = attn + (long long)bn * MM;
    for (int m = t; m < MM; m += 256) {
        float a = __expf(sm[m] - mx[0]) * rs[0]
                + __expf(sm[MM + m] - mx[1]) * rs[1]
                + __expf(sm[2 * MM + m] - mx[2]) * rs[2]
                + __expf(sm[3 * MM + m] - mx[3]) * rs[3];
        dst[m] = a; ss += a * a;
    }
    red[t] = ss; __syncthreads();
    for (int k = 128; k > 0; k >>= 1) { if (t < k) red[t] += red[t + k]; __syncthreads(); }
    if (t == 0) { float nr = sqrtf(red[0]); invn[bn] = 1.0f / fmaxf(nr, 1e-12f); }
}

// ---------------- diversity: sum_m (sum_n attn[b,n,m]*invn[b,n])^2, two-stage ----------------
__global__ void div_s_kernel(const float* __restrict__ attn, const float* __restrict__ invn)
{
    __shared__ float sinv[304];
    __shared__ float red[256];
    int b = blockIdx.y, t = threadIdx.x;
    for (int i = t; i < NN; i += 256) sinv[i] = invn[b * NN + i];
    __syncthreads();
    int m = blockIdx.x * 256 + t;
    const float* base = attn + (long long)b * NN * MM + m;
    float s = 0.f;
    for (int n = 0; n < NN; n++) s += base[(long long)n * MM] * sinv[n];
    red[t] = s * s; __syncthreads();
    for (int k = 128; k > 0; k >>= 1) { if (t < k) red[t] += red[t + k]; __syncthreads(); }
    if (t == 0) g_divpart[b * 16 + blockIdx.x] = red[0];
}

__global__ void finalize_div(float* __restrict__ outdiv)
{
    __shared__ float red[256];
    int t = threadIdx.x;
    red[t] = g_divpart[t]; __syncthreads();
    for (int k = 128; k > 0; k >>= 1) { if (t < k) red[t] += red[t + k]; __syncthreads(); }
    if (t == 0) outdiv[0] = (red[0] - (float)(BB * NN)) * (0.1f / ((float)NN * (NN - 1)));
}

// ---------------- reduce split-K partials; write aligned sf buffer + d_out sf ----------------
__global__ void reduce_sf(const float* __restrict__ part, float* __restrict__ sfb,
                          float* __restrict__ outsf)
{
    long long i = (long long)blockIdx.x * 256 + threadIdx.x;  // 16*76800 total
    if (i >= (long long)BB * NN * HID) return;
    long long z = i / (NN * HID), r = i - z * (NN * HID);
    const float* p = part + z * 8LL * (NN * HID) + r;
    float s = 0.f;
#pragma unroll
    for (int k = 0; k < 8; k++) s += p[(long long)k * (NN * HID)];
    sfb[i] = s; outsf[i] = s;
}

// ---------------- LayerNorm(256) + ReLU, in place ----------------
__global__ void ln_relu_kernel(float* __restrict__ z, const float* __restrict__ g,
                               const float* __restrict__ bb)
{
    __shared__ float red[256];
    __shared__ float mu_s, var_s;
    int row = blockIdx.x, t = threadIdx.x;
    float v = z[(long long)row * 256 + t];
    red[t] = v; __syncthreads();
    for (int k = 128; k > 0; k >>= 1) { if (t < k) red[t] += red[t + k]; __syncthreads(); }
    if (t == 0) mu_s = red[0] * (1.0f / 256.0f);
    __syncthreads();
    float d = v - mu_s;
    red[t] = d * d; __syncthreads();
    for (int k = 128; k > 0; k >>= 1) { if (t < k) red[t] += red[t + k]; __syncthreads(); }
    if (t == 0) var_s = red[0] * (1.0f / 256.0f);
    __syncthreads();
    float o = d * rsqrtf(var_s + 1e-5f) * g[t] + bb[t];
    z[(long long)row * 256 + t] = fmaxf(o, 0.f);
}

// ---------------- host ----------------
extern "C" void kernel_launch(void* const* d_in, const int* in_sizes, int n_in,
                              void* d_out_, int out_size)
{
    const float* x      = (const float*)d_in[0];
    const float* q      = (const float*)d_in[1];
    const float* pos_w  = (const float*)d_in[2];
    const float* pos_b  = (const float*)d_in[3];
    const float* fp_w   = (const float*)d_in[4];
    const float* fp_b   = (const float*)d_in[5];
    const float* bn_g   = (const float*)d_in[6];
    const float* bn_b   = (const float*)d_in[7];
    const float* bn_m   = (const float*)d_in[8];
    const float* bn_v   = (const float*)d_in[9];
    const float* key_w  = (const float*)d_in[10];
    const float* key_b  = (const float*)d_in[11];
    const float* val_w  = (const float*)d_in[12];
    const float* val_b  = (const float*)d_in[13];
    const float* ctp_w  = (const float*)d_in[14];
    const float* ctp_b  = (const float*)d_in[15];
    const float* bb1_w  = (const float*)d_in[16];
    const float* bb1_b  = (const float*)d_in[17];
    const float* bbln_g = (const float*)d_in[18];
    const float* bbln_b = (const float*)d_in[19];
    const float* bb2_w  = (const float*)d_in[20];
    const float* bb2_b  = (const float*)d_in[21];
    const float* bb3_w  = (const float*)d_in[22];
    const float* bb3_b  = (const float*)d_in[23];
    const float* ch1_w  = (const float*)d_in[24];
    const float* ch1_b  = (const float*)d_in[25];
    const float* chln_g = (const float*)d_in[26];
    const float* chln_b = (const float*)d_in[27];
    const float* ch2_w  = (const float*)d_in[28];
    const float* ch2_b  = (const float*)d_in[29];
    const float* ch3_w  = (const float*)d_in[30];
    const float* ch3_b  = (const float*)d_in[31];
    float* out = (float*)d_out_;

    float *feats, *keys, *vals, *pos, *posk, *posv, *logits, *invn, *sfp, *sfb, *h1, *h2, *bns, *bnt;
    cudaGetSymbolAddress((void**)&feats,  g_feats);
    cudaGetSymbolAddress((void**)&keys,   g_keys);
    cudaGetSymbolAddress((void**)&vals,   g_vals);
    cudaGetSymbolAddress((void**)&pos,    g_pos);
    cudaGetSymbolAddress((void**)&posk,   g_posk);
    cudaGetSymbolAddress((void**)&posv,   g_posv);
    cudaGetSymbolAddress((void**)&logits, g_logits);
    cudaGetSymbolAddress((void**)&invn,   g_invn);
    cudaGetSymbolAddress((void**)&sfp,    g_sfp);
    cudaGetSymbolAddress((void**)&sfb,    g_sf);
    cudaGetSymbolAddress((void**)&h1,     g_h1);
    cudaGetSymbolAddress((void**)&h2,     g_h2);
    cudaGetSymbolAddress((void**)&bns,    g_bns);
    cudaGetSymbolAddress((void**)&bnt,    g_bnt);

    cudaFuncSetAttribute(softmax_kernel, cudaFuncAttributeMaxDynamicSharedMemorySize, 4 * MM * 4);

    // 1. BN fold
    init_kernel<<<1, 128>>>(fp_b, bn_g, bn_b, bn_m, bn_v);
    // 2. positional channels (128 x 4096)
    pos_kernel<<<dim3(16, 128), 256>>>(pos_w, pos_b);
    // 3. batch-invariant pos contributions (include biases)
    gemm_nn<0, 0><<<dim3(32, 1, 1), 256>>>(key_w + 128, 256, pos, posk, 64, MM, 128,
                                           0, 0, 0, key_b, nullptr, 1.f, nullptr);
    gemm_nn<0, 0><<<dim3(32, 2, 1), 256>>>(val_w + 128, 256, pos, posv, 256, MM, 128,
                                           0, 0, 0, val_b, nullptr, 1.f, nullptr);
    // 4. feats = relu(bn(fp_w[:128] @ x))  (only first 128 channels are consumed downstream)
    gemm_nn<1, 0><<<dim3(32, 1, BB), 256>>>(fp_w, 256, x, feats, 128, MM, 256,
                                            0, (long long)CC * MM, 128LL * MM, bns, bnt, 1.f, nullptr);
    // 5. keys = key_w[:, :128] @ feats + posk ; vals likewise
    gemm_nn<2, 0><<<dim3(32, 1, BB), 256>>>(key_w, 256, feats, keys, 64, MM, 128,
                                            0, 128LL * MM, 64LL * MM, nullptr, nullptr, 1.f, posk);
    gemm_nn<2, 0><<<dim3(32, 2, BB), 256>>>(val_w, 256, feats, vals, 256, MM, 128,
                                            0, 128LL * MM, 256LL * MM, nullptr, nullptr, 1.f, posv);
    // 6. logits[b,h,n,m] = 0.25 * q_h @ keys_h
    gemm_nn<0, 1><<<dim3(32, 3, BB * 4), 256>>>(q, 64, keys, logits, NN, MM, 16,
                                                0, 0, 0, nullptr, nullptr, 0.25f, nullptr);
    // 7. softmax + head-mean -> maps region of d_out; per-row inv-norms
    softmax_kernel<<<BB * NN, 256, 4 * MM * 4>>>(logits, out + OFF_MAPS, invn);
    // 8. diversity scalar (closed form: sum_m s^2 - B*N)
    div_s_kernel<<<dim3(16, BB), 256>>>(out + OFF_MAPS, invn);
    finalize_div<<<1, 256>>>(out + OFF_DIV);
    // 9. sf = attn @ vals^T  (split-K=8, deterministic two-phase)
    gemm_nt<0, true><<<dim3(2, 3, BB * 8), 256>>>(out + OFF_MAPS, vals, sfp, NN, HID, MM,
                                                  (long long)NN * MM, (long long)HID * MM,
                                                  8LL * NN * HID, nullptr, 8, (long long)NN * HID);
    reduce_sf<<<4800, 256>>>(sfp, sfb, out + OFF_SF);
    // 10. box head
    gemm_nt<0, false><<<dim3(2, 38, 1), 256>>>(sfb, bb1_w, h1, BB * NN, 256, 256, 0, 0, 0, bb1_b, 1, 0);
    ln_relu_kernel<<<BB * NN, 256>>>(h1, bbln_g, bbln_b);
    gemm_nt<1, false><<<dim3(1, 38, 1), 256>>>(h1, bb2_w, h2, BB * NN, 128, 256, 0, 0, 0, bb2_b, 1, 0);
    gemm_nt<0, false><<<dim3(1, 38, 1), 256>>>(h2, bb3_w, out + OFF_BOXES, BB * NN, 4, 128, 0, 0, 0, bb3_b, 1, 0);
    // 11. score head
    gemm_nt<0, false><<<dim3(2, 38, 1), 256>>>(sfb, ch1_w, h1, BB * NN, 256, 256, 0, 0, 0, ch1_b, 1, 0);
    ln_relu_kernel<<<BB * NN, 256>>>(h1, chln_g, chln_b);
    gemm_nt<1, false><<<dim3(1, 38, 1), 256>>>(h1, ch2_w, h2, BB * NN, 128, 256, 0, 0, 0, ch2_b, 1, 0);
    gemm_nt<2, false><<<dim3(1, 38, 1), 256>>>(h2, ch3_w, out + OFF_SCORES, BB * NN, 1, 128, 0, 0, 0, ch3_b, 1, 0);
    // 12. class head
    gemm_nt<0, false><<<dim3(1, 38, 1), 256>>>(sfb, ctp_w, out + OFF_CLS, BB * NN, NCC, 256, 0, 0, 0, ctp_b, 1, 0);
}

// round 3
// speedup vs baseline: 1.1548x; 1.1548x over previous
#include <cuda_runtime.h>
#include <cstdint>
#include <math.h>

// ---------------- problem constants ----------------
#define BB   16
#define CC   256
#define MM   4096          // H*W
#define HID  256
#define NN   300
#define NCC  80

// output layout (flattened tuple: boxes, scores, cls, maps, div, sf)
#define OFF_BOXES  0LL
#define OFF_SCORES 19200LL
#define OFF_CLS    24000LL
#define OFF_MAPS   408000LL
#define OFF_DIV    20068800LL
#define OFF_SF     20068801LL

// ---------------- device scratch ----------------
__device__ float g_feats[BB * 128 * MM];
__device__ float g_keys [BB * 64 * MM];
__device__ float g_vals [BB * 256 * MM];
__device__ float g_pos  [128 * MM];
__device__ float g_posk [64 * MM];
__device__ float g_posv [256 * MM];
__device__ float g_logits[(long long)BB * 4 * NN * MM];
__device__ float g_invn [BB * NN];
__device__ float g_sf   [BB * NN * HID];
__device__ float g_h1   [BB * NN * 256];
__device__ float g_h2   [BB * NN * 128];
__device__ float g_bns  [128];
__device__ float g_bnt  [128];
__device__ float g_divpart[256];

__device__ __forceinline__ float tf32_rna(float v) {
    uint32_t u;
    asm("cvt.rna.tf32.f32 %0, %1;" : "=r"(u) : "f"(v));
    return __uint_as_float(u);
}
__device__ __forceinline__ float4 cvt4(float4 v) {
    v.x = tf32_rna(v.x); v.y = tf32_rna(v.y);
    v.z = tf32_rna(v.z); v.w = tf32_rna(v.w);
    return v;
}
__device__ __forceinline__ void mma_tf32(float c[4], const uint32_t a[4], const uint32_t b[2]) {
    asm volatile(
        "mma.sync.aligned.m16n8k8.row.col.f32.tf32.tf32.f32 "
        "{%0,%1,%2,%3}, {%4,%5,%6,%7}, {%8,%9}, {%0,%1,%2,%3};"
        : "+f"(c[0]), "+f"(c[1]), "+f"(c[2]), "+f"(c[3])
        : "r"(a[0]), "r"(a[1]), "r"(a[2]), "r"(a[3]), "r"(b[0]), "r"(b[1]));
}

// ---------------- small kernels ----------------
__global__ void init_kernel(const float* __restrict__ fp_b, const float* __restrict__ bn_g,
                            const float* __restrict__ bn_b, const float* __restrict__ bn_m,
                            const float* __restrict__ bn_v) {
    int t = threadIdx.x;
    if (t < 128) {
        float s = bn_g[t] * rsqrtf(bn_v[t] + 1e-5f);
        g_bns[t] = s;
        g_bnt[t] = (fp_b[t] - bn_m[t]) * s + bn_b[t];
    }
}

__global__ void pos_kernel(const float* __restrict__ pos_w, const float* __restrict__ pos_b) {
    int m = blockIdx.x * 256 + threadIdx.x;
    int o = blockIdx.y;
    int hh = m >> 6, ww = m & 63;
    float y = -1.0f + 2.0f * (float)hh / 63.0f;
    float x = -1.0f + 2.0f * (float)ww / 63.0f;
    g_pos[(long long)o * MM + m] = pos_w[o * 2] * y + pos_w[o * 2 + 1] * x + pos_b[o];
}

// ---------------- SIMT GEMM NN ----------------
#define TILE 128
#define BK   16

template<int EPI, int ZMAP>
__global__ void __launch_bounds__(256) gemm_nn(
    const float* __restrict__ Wb, int ldw,
    const float* __restrict__ Xb, float* __restrict__ Cb,
    int O, int M, int K,
    long long wz, long long xz, long long cz,
    const float* __restrict__ v1, const float* __restrict__ v2,
    float alpha, const float* __restrict__ C0)
{
    __shared__ float Ws[BK][TILE + 4];
    __shared__ float Xs[BK][TILE + 4];
    int z = blockIdx.z;
    const float* W; const float* X; float* C;
    if (ZMAP == 0) { W = Wb + wz * z; X = Xb + xz * z; C = Cb + cz * z; }
    else {
        int b = z >> 2, h = z & 3;
        W = Wb + h * 16;
        X = Xb + ((long long)(b * 64 + h * 16)) * M;
        C = Cb + (long long)z * O * M;
    }
    int t = threadIdx.x, tx = t & 15, ty = t >> 4;
    int oB = blockIdx.y * TILE, mB = blockIdx.x * TILE;

    float acc[8][8];
#pragma unroll
    for (int i = 0; i < 8; i++)
#pragma unroll
        for (int j = 0; j < 8; j++) acc[i][j] = 0.f;

    for (int k0 = 0; k0 < K; k0 += BK) {
#pragma unroll
        for (int r = 0; r < 2; r++) {
            int idx = t + r * 256;
            int row = idx >> 2, kq = (idx & 3) * 4;
            float4 v = make_float4(0.f, 0.f, 0.f, 0.f);
            int o = oB + row;
            if (o < O) v = *(const float4*)(W + (long long)o * ldw + k0 + kq);
            Ws[kq + 0][row] = v.x; Ws[kq + 1][row] = v.y;
            Ws[kq + 2][row] = v.z; Ws[kq + 3][row] = v.w;
        }
#pragma unroll
        for (int r = 0; r < 2; r++) {
            int idx = t + r * 256;
            int row = idx >> 5, cq = (idx & 31) * 4;
            float4 v = *(const float4*)(X + (long long)(k0 + row) * M + mB + cq);
            *(float4*)&Xs[row][cq] = v;
        }
        __syncthreads();
#pragma unroll
        for (int k = 0; k < BK; k++) {
            float a[8], bv[8];
            *(float4*)&a[0]  = *(const float4*)&Ws[k][ty * 4];
            *(float4*)&a[4]  = *(const float4*)&Ws[k][ty * 4 + 64];
            *(float4*)&bv[0] = *(const float4*)&Xs[k][tx * 4];
            *(float4*)&bv[4] = *(const float4*)&Xs[k][tx * 4 + 64];
#pragma unroll
            for (int i = 0; i < 8; i++)
#pragma unroll
                for (int j = 0; j < 8; j++) acc[i][j] += a[i] * bv[j];
        }
        __syncthreads();
    }
#pragma unroll
    for (int i = 0; i < 8; i++) {
        int o = oB + (i < 4 ? ty * 4 + i : 64 + ty * 4 + i - 4);
        if (o >= O) continue;
        float e1 = 0.f, e2 = 0.f, bo = 0.f;
        if (EPI == 1) { e1 = v1[o]; e2 = v2[o]; }
        if (EPI == 0 && v1) bo = v1[o];
#pragma unroll
        for (int j = 0; j < 8; j++) {
            int m = mB + (j < 4 ? tx * 4 + j : 64 + tx * 4 + j - 4);
            if (m >= M) continue;
            float v = acc[i][j];
            if (EPI == 0)      v = alpha * v + bo;
            else if (EPI == 1) v = fmaxf(v * e1 + e2, 0.f);
            else               v = v + C0[(long long)o * M + m];
            C[(long long)o * M + m] = v;
        }
    }
}

// ---------------- SIMT GEMM NT (heads) ----------------
template<int EPI>
__global__ void __launch_bounds__(256) gemm_nt(
    const float* __restrict__ Ab, const float* __restrict__ Bb, float* __restrict__ Cb,
    int I, int J, int K, const float* __restrict__ bias)
{
    __shared__ float As[BK][TILE + 4];
    __shared__ float Bs[BK][TILE + 4];
    int t = threadIdx.x, tx = t & 15, ty = t >> 4;
    int iB = blockIdx.y * TILE, jB = blockIdx.x * TILE;

    float acc[8][8];
#pragma unroll
    for (int i = 0; i < 8; i++)
#pragma unroll
        for (int j = 0; j < 8; j++) acc[i][j] = 0.f;

    for (int k0 = 0; k0 < K; k0 += BK) {
#pragma unroll
        for (int r = 0; r < 2; r++) {
            int idx = t + r * 256;
            int row = idx >> 2, kq = (idx & 3) * 4;
            float4 v = make_float4(0.f, 0.f, 0.f, 0.f);
            int i = iB + row;
            if (i < I) v = *(const float4*)(Ab + (long long)i * K + k0 + kq);
            As[kq + 0][row] = v.x; As[kq + 1][row] = v.y;
            As[kq + 2][row] = v.z; As[kq + 3][row] = v.w;
        }
#pragma unroll
        for (int r = 0; r < 2; r++) {
            int idx = t + r * 256;
            int row = idx >> 2, kq = (idx & 3) * 4;
            float4 v = make_float4(0.f, 0.f, 0.f, 0.f);
            int j = jB + row;
            if (j < J) v = *(const float4*)(Bb + (long long)j * K + k0 + kq);
            Bs[kq + 0][row] = v.x; Bs[kq + 1][row] = v.y;
            Bs[kq + 2][row] = v.z; Bs[kq + 3][row] = v.w;
        }
        __syncthreads();
#pragma unroll
        for (int k = 0; k < BK; k++) {
            float a[8], bv[8];
            *(float4*)&a[0]  = *(const float4*)&As[k][ty * 4];
            *(float4*)&a[4]  = *(const float4*)&As[k][ty * 4 + 64];
            *(float4*)&bv[0] = *(const float4*)&Bs[k][tx * 4];
            *(float4*)&bv[4] = *(const float4*)&Bs[k][tx * 4 + 64];
#pragma unroll
            for (int i = 0; i < 8; i++)
#pragma unroll
                for (int j = 0; j < 8; j++) acc[i][j] += a[i] * bv[j];
        }
        __syncthreads();
    }
#pragma unroll
    for (int i = 0; i < 8; i++) {
        int ii = iB + (i < 4 ? ty * 4 + i : 64 + ty * 4 + i - 4);
        if (ii >= I) continue;
#pragma unroll
        for (int j = 0; j < 8; j++) {
            int jj = jB + (j < 4 ? tx * 4 + j : 64 + tx * 4 + j - 4);
            if (jj >= J) continue;
            float v = acc[i][j];
            if (bias) v += bias[jj];
            if (EPI == 1) v = fmaxf(v, 0.f);
            else if (EPI == 2) v = 1.0f / (1.0f + __expf(-v));
            Cb[(long long)ii * J + jj] = v;
        }
    }
}

// ---------------- softmax over m (4096), per (b,n); head-mean; row inv-norm ----------------
__global__ void softmax_kernel(const float* __restrict__ logits,
                               float* __restrict__ attn, float* __restrict__ invn)
{
    extern __shared__ float sm[];
    __shared__ float red[256];
    int bn = blockIdx.x;
    int b = bn / NN, n = bn - b * NN;
    int t = threadIdx.x;
#pragma unroll
    for (int h = 0; h < 4; h++) {
        const float* src = logits + ((long long)(b * 4 + h) * NN + n) * MM;
        for (int m = t; m < MM; m += 256) sm[h * MM + m] = src[m];
    }
    __syncthreads();
    float mx[4], rs[4];
#pragma unroll
    for (int h = 0; h < 4; h++) {
        float lm = -1e30f;
        for (int m = t; m < MM; m += 256) lm = fmaxf(lm, sm[h * MM + m]);
        red[t] = lm; __syncthreads();
        for (int k = 128; k > 0; k >>= 1) { if (t < k) red[t] = fmaxf(red[t], red[t + k]); __syncthreads(); }
        mx[h] = red[0]; __syncthreads();
        float ls = 0.f;
        for (int m = t; m < MM; m += 256) ls += __expf(sm[h * MM + m] - mx[h]);
        red[t] = ls; __syncthreads();
        for (int k = 128; k > 0; k >>= 1) { if (t < k) red[t] += red[t + k]; __syncthreads(); }
        rs[h] = 0.25f / red[0]; __syncthreads();
    }
    float ss = 0.f;
    float* dst = attn + (long long)bn * MM;
    for (int m = t; m < MM; m += 256) {
        float a = __expf(sm[m] - mx[0]) * rs[0]
                + __expf(sm[MM + m] - mx[1]) * rs[1]
                + __expf(sm[2 * MM + m] - mx[2]) * rs[2]
                + __expf(sm[3 * MM + m] - mx[3]) * rs[3];
        dst[m] = a; ss += a * a;
    }
    red[t] = ss; __syncthreads();
    for (int k = 128; k > 0; k >>= 1) { if (t < k) red[t] += red[t + k]; __syncthreads(); }
    if (t == 0) { float nr = sqrtf(red[0]); invn[bn] = 1.0f / fmaxf(nr, 1e-12f); }
}

// ---------------- diversity ----------------
__global__ void div_s_kernel(const float* __restrict__ attn, const float* __restrict__ invn)
{
    __shared__ float sinv[304];
    __shared__ float red[256];
    int b = blockIdx.y, t = threadIdx.x;
    for (int i = t; i < NN; i += 256) sinv[i] = invn[b * NN + i];
    __syncthreads();
    int m = blockIdx.x * 256 + t;
    const float* base = attn + (long long)b * NN * MM + m;
    float s = 0.f;
    for (int n = 0; n < NN; n++) s += base[(long long)n * MM] * sinv[n];
    red[t] = s * s; __syncthreads();
    for (int k = 128; k > 0; k >>= 1) { if (t < k) red[t] += red[t + k]; __syncthreads(); }
    if (t == 0) g_divpart[b * 16 + blockIdx.x] = red[0];
}

__global__ void finalize_div(float* __restrict__ outdiv)
{
    __shared__ float red[256];
    int t = threadIdx.x;
    red[t] = g_divpart[t]; __syncthreads();
    for (int k = 128; k > 0; k >>= 1) { if (t < k) red[t] += red[t + k]; __syncthreads(); }
    if (t == 0) outdiv[0] = (red[0] - (float)(BB * NN)) * (0.1f / ((float)NN * (NN - 1)));
}

// ---------------- LayerNorm(256) + ReLU, in place ----------------
__global__ void ln_relu_kernel(float* __restrict__ z, const float* __restrict__ g,
                               const float* __restrict__ bb)
{
    __shared__ float red[256];
    __shared__ float mu_s, var_s;
    int row = blockIdx.x, t = threadIdx.x;
    float v = z[(long long)row * 256 + t];
    red[t] = v; __syncthreads();
    for (int k = 128; k > 0; k >>= 1) { if (t < k) red[t] += red[t + k]; __syncthreads(); }
    if (t == 0) mu_s = red[0] * (1.0f / 256.0f);
    __syncthreads();
    float d = v - mu_s;
    red[t] = d * d; __syncthreads();
    for (int k = 128; k > 0; k >>= 1) { if (t < k) red[t] += red[t + k]; __syncthreads(); }
    if (t == 0) var_s = red[0] * (1.0f / 256.0f);
    __syncthreads();
    float o = d * rsqrtf(var_s + 1e-5f) * g[t] + bb[t];
    z[(long long)row * 256 + t] = fmaxf(o, 0.f);
}

// ================= mma.sync tf32 GEMM: sf = attn @ vals^T =================
// Block: 256 thr (8 warps, 4n x 2c). Tile 128n x 128c, K chunks of 32, double-buffered.
// smem row stride 36 floats: conflict-free frag loads, 16B-aligned float4 stores.
#define SF_ROWF 36
#define SF_BUF  (128 * SF_ROWF)                 // floats per buffer
#define SF_SMEM (4 * SF_BUF * 4)                // 2 A bufs + 2 B bufs, bytes = 73728

__global__ void __launch_bounds__(256, 1) sf_hmma_kernel(
    const float* __restrict__ attn, const float* __restrict__ vals,
    float* __restrict__ sfb, float* __restrict__ outsf)
{
    extern __shared__ float smf[];
    float* As = smf;                 // [2][128][36]
    float* Bs = smf + 2 * SF_BUF;    // [2][128][36]
    int t = threadIdx.x;
    int lane = t & 31, w = t >> 5;
    int wn0 = (w & 3) * 32, wc0 = (w >> 2) * 64;
    int g = lane >> 2, tq = lane & 3;
    int n0 = blockIdx.y * 128, c0 = blockIdx.x * 128, b = blockIdx.z;

    int col4 = (t & 7) * 4;          // 0..28, float4 column within 32-chunk
    int row0 = t >> 3;               // 0..31

    const float* Ab = attn + (long long)b * NN * MM;
    const float* Bb = vals + (long long)b * HID * MM;

    float acc[2][8][4];
#pragma unroll
    for (int mi = 0; mi < 2; mi++)
#pragma unroll
        for (int ni = 0; ni < 8; ni++)
#pragma unroll
            for (int r = 0; r < 4; r++) acc[mi][ni][r] = 0.f;

    float4 ra[4], rb[4];
    // prologue: load chunk 0
#pragma unroll
    for (int i = 0; i < 4; i++) {
        int r = row0 + 32 * i;
        int an = n0 + r; if (an > NN - 1) an = NN - 1;
        ra[i] = *(const float4*)(Ab + (long long)an * MM + col4);
        rb[i] = *(const float4*)(Bb + (long long)(c0 + r) * MM + col4);
    }
#pragma unroll
    for (int i = 0; i < 4; i++) {
        int r = row0 + 32 * i;
        *(float4*)&As[r * SF_ROWF + col4] = cvt4(ra[i]);
        *(float4*)&Bs[r * SF_ROWF + col4] = cvt4(rb[i]);
    }
    __syncthreads();

    for (int ch = 0; ch < MM / 32; ch++) {
        int buf = ch & 1;
        bool more = (ch + 1) < MM / 32;
        if (more) {
            int k0 = (ch + 1) * 32 + col4;
#pragma unroll
            for (int i = 0; i < 4; i++) {
                int r = row0 + 32 * i;
                int an = n0 + r; if (an > NN - 1) an = NN - 1;
                ra[i] = *(const float4*)(Ab + (long long)an * MM + k0);
                rb[i] = *(const float4*)(Bb + (long long)(c0 + r) * MM + k0);
            }
        }
        const uint32_t* Asu = (const uint32_t*)(As + buf * SF_BUF);
        const uint32_t* Bsu = (const uint32_t*)(Bs + buf * SF_BUF);
#pragma unroll
        for (int ks = 0; ks < 4; ks++) {
            int kk = ks * 8 + tq;
            uint32_t a[2][4];
#pragma unroll
            for (int mi = 0; mi < 2; mi++) {
                int r = wn0 + 16 * mi + g;
                a[mi][0] = Asu[r * SF_ROWF + kk];
                a[mi][1] = Asu[(r + 8) * SF_ROWF + kk];
                a[mi][2] = Asu[r * SF_ROWF + kk + 4];
                a[mi][3] = Asu[(r + 8) * SF_ROWF + kk + 4];
            }
            uint32_t bf[8][2];
#pragma unroll
            for (int ni = 0; ni < 8; ni++) {
                int c = wc0 + ni * 8 + g;
                bf[ni][0] = Bsu[c * SF_ROWF + kk];
                bf[ni][1] = Bsu[c * SF_ROWF + kk + 4];
            }
#pragma unroll
            for (int mi = 0; mi < 2; mi++)
#pragma unroll
                for (int ni = 0; ni < 8; ni++)
                    mma_tf32(acc[mi][ni], a[mi], bf[ni]);
        }
        if (more) {
            float* Ad = As + (buf ^ 1) * SF_BUF;
            float* Bd = Bs + (buf ^ 1) * SF_BUF;
#pragma unroll
            for (int i = 0; i < 4; i++) {
                int r = row0 + 32 * i;
                *(float4*)&Ad[r * SF_ROWF + col4] = cvt4(ra[i]);
                *(float4*)&Bd[r * SF_ROWF + col4] = cvt4(rb[i]);
            }
        }
        __syncthreads();
    }

    // epilogue
#pragma unroll
    for (int mi = 0; mi < 2; mi++) {
#pragma unroll
        for (int ni = 0; ni < 8; ni++) {
            int c = c0 + wc0 + ni * 8 + 2 * tq;
            int n1 = n0 + wn0 + 16 * mi + g;
            if (n1 < NN) {
                long long o = ((long long)b * NN + n1) * HID + c;
                float2 v = make_float2(acc[mi][ni][0], acc[mi][ni][1]);
                *(float2*)(sfb + o) = v;
                outsf[o] = v.x; outsf[o + 1] = v.y;
            }
            int n2 = n1 + 8;
            if (n2 < NN) {
                long long o = ((long long)b * NN + n2) * HID + c;
                float2 v = make_float2(acc[mi][ni][2], acc[mi][ni][3]);
                *(float2*)(sfb + o) = v;
                outsf[o] = v.x; outsf[o + 1] = v.y;
            }
        }
    }
}

// ---------------- host ----------------
extern "C" void kernel_launch(void* const* d_in, const int* in_sizes, int n_in,
                              void* d_out_, int out_size)
{
    const float* x      = (const float*)d_in[0];
    const float* q      = (const float*)d_in[1];
    const float* pos_w  = (const float*)d_in[2];
    const float* pos_b  = (const float*)d_in[3];
    const float* fp_w   = (const float*)d_in[4];
    const float* fp_b   = (const float*)d_in[5];
    const float* bn_g   = (const float*)d_in[6];
    const float* bn_b   = (const float*)d_in[7];
    const float* bn_m   = (const float*)d_in[8];
    const float* bn_v   = (const float*)d_in[9];
    const float* key_w  = (const float*)d_in[10];
    const float* key_b  = (const float*)d_in[11];
    const float* val_w  = (const float*)d_in[12];
    const float* val_b  = (const float*)d_in[13];
    const float* ctp_w  = (const float*)d_in[14];
    const float* ctp_b  = (const float*)d_in[15];
    const float* bb1_w  = (const float*)d_in[16];
    const float* bb1_b  = (const float*)d_in[17];
    const float* bbln_g = (const float*)d_in[18];
    const float* bbln_b = (const float*)d_in[19];
    const float* bb2_w  = (const float*)d_in[20];
    const float* bb2_b  = (const float*)d_in[21];
    const float* bb3_w  = (const float*)d_in[22];
    const float* bb3_b  = (const float*)d_in[23];
    const float* ch1_w  = (const float*)d_in[24];
    const float* ch1_b  = (const float*)d_in[25];
    const float* chln_g = (const float*)d_in[26];
    const float* chln_b = (const float*)d_in[27];
    const float* ch2_w  = (const float*)d_in[28];
    const float* ch2_b  = (const float*)d_in[29];
    const float* ch3_w  = (const float*)d_in[30];
    const float* ch3_b  = (const float*)d_in[31];
    float* out = (float*)d_out_;

    float *feats, *keys, *vals, *pos, *posk, *posv, *logits, *invn, *sfb, *h1, *h2, *bns, *bnt;
    cudaGetSymbolAddress((void**)&feats,  g_feats);
    cudaGetSymbolAddress((void**)&keys,   g_keys);
    cudaGetSymbolAddress((void**)&vals,   g_vals);
    cudaGetSymbolAddress((void**)&pos,    g_pos);
    cudaGetSymbolAddress((void**)&posk,   g_posk);
    cudaGetSymbolAddress((void**)&posv,   g_posv);
    cudaGetSymbolAddress((void**)&logits, g_logits);
    cudaGetSymbolAddress((void**)&invn,   g_invn);
    cudaGetSymbolAddress((void**)&sfb,    g_sf);
    cudaGetSymbolAddress((void**)&h1,     g_h1);
    cudaGetSymbolAddress((void**)&h2,     g_h2);
    cudaGetSymbolAddress((void**)&bns,    g_bns);
    cudaGetSymbolAddress((void**)&bnt,    g_bnt);

    cudaFuncSetAttribute(softmax_kernel, cudaFuncAttributeMaxDynamicSharedMemorySize, 4 * MM * 4);
    cudaFuncSetAttribute(sf_hmma_kernel, cudaFuncAttributeMaxDynamicSharedMemorySize, SF_SMEM);

    // 1. BN fold
    init_kernel<<<1, 128>>>(fp_b, bn_g, bn_b, bn_m, bn_v);
    // 2. positional channels
    pos_kernel<<<dim3(16, 128), 256>>>(pos_w, pos_b);
    // 3. batch-invariant pos contributions (include biases)
    gemm_nn<0, 0><<<dim3(32, 1, 1), 256>>>(key_w + 128, 256, pos, posk, 64, MM, 128,
                                           0, 0, 0, key_b, nullptr, 1.f, nullptr);
    gemm_nn<0, 0><<<dim3(32, 2, 1), 256>>>(val_w + 128, 256, pos, posv, 256, MM, 128,
                                           0, 0, 0, val_b, nullptr, 1.f, nullptr);
    // 4. feats = relu(bn(fp_w[:128] @ x))
    gemm_nn<1, 0><<<dim3(32, 1, BB), 256>>>(fp_w, 256, x, feats, 128, MM, 256,
                                            0, (long long)CC * MM, 128LL * MM, bns, bnt, 1.f, nullptr);
    // 5. keys/vals
    gemm_nn<2, 0><<<dim3(32, 1, BB), 256>>>(key_w, 256, feats, keys, 64, MM, 128,
                                            0, 128LL * MM, 64LL * MM, nullptr, nullptr, 1.f, posk);
    gemm_nn<2, 0><<<dim3(32, 2, BB), 256>>>(val_w, 256, feats, vals, 256, MM, 128,
                                            0, 128LL * MM, 256LL * MM, nullptr, nullptr, 1.f, posv);
    // 6. logits
    gemm_nn<0, 1><<<dim3(32, 3, BB * 4), 256>>>(q, 64, keys, logits, NN, MM, 16,
                                                0, 0, 0, nullptr, nullptr, 0.25f, nullptr);
    // 7. softmax + head-mean -> maps region of d_out
    softmax_kernel<<<BB * NN, 256, 4 * MM * 4>>>(logits, out + OFF_MAPS, invn);
    // 8. diversity
    div_s_kernel<<<dim3(16, BB), 256>>>(out + OFF_MAPS, invn);
    finalize_div<<<1, 256>>>(out + OFF_DIV);
    // 9. sf = attn @ vals^T — mma.sync tf32
    sf_hmma_kernel<<<dim3(2, 3, BB), 256, SF_SMEM>>>(out + OFF_MAPS, vals, sfb, out + OFF_SF);
    // 10. box head
    gemm_nt<0><<<dim3(2, 38, 1), 256>>>(sfb, bb1_w, h1, BB * NN, 256, 256, bb1_b);
    ln_relu_kernel<<<BB * NN, 256>>>(h1, bbln_g, bbln_b);
    gemm_nt<1><<<dim3(1, 38, 1), 256>>>(h1, bb2_w, h2, BB * NN, 128, 256, bb2_b);
    gemm_nt<0><<<dim3(1, 38, 1), 256>>>(h2, bb3_w, out + OFF_BOXES, BB * NN, 4, 128, bb3_b);
    // 11. score head
    gemm_nt<0><<<dim3(2, 38, 1), 256>>>(sfb, ch1_w, h1, BB * NN, 256, 256, ch1_b);
    ln_relu_kernel<<<BB * NN, 256>>>(h1, chln_g, chln_b);
    gemm_nt<1><<<dim3(1, 38, 1), 256>>>(h1, ch2_w, h2, BB * NN, 128, 256, ch2_b);
    gemm_nt<2><<<dim3(1, 38, 1), 256>>>(h2, ch3_w, out + OFF_SCORES, BB * NN, 1, 128, ch3_b);
    // 12. class head
    gemm_nt<0><<<dim3(1, 38, 1), 256>>>(sfb, ctp_w, out + OFF_CLS, BB * NN, NCC, 256, ctp_b);
}